// round 1
// baseline (speedup 1.0000x reference)
#include <cuda_runtime.h>
#include <cuda_bf16.h>
#include <cstdint>

// Problem constants
#define BATCH 8
#define CCH   64      // channels C
#define DQ    8       // q/k dim
#define NPIX  4096    // H*W
#define TM    128     // m rows per CTA
#define TN    128     // n tile size

// Scratch: q,k as [b][n][8], v as [b][n][64] (n-major for coalesced tile loads)
__device__ float g_q[BATCH * NPIX * DQ];
__device__ float g_k[BATCH * NPIX * DQ];
__device__ float g_v[(size_t)BATCH * NPIX * CCH];

// ---------------------------------------------------------------------------
// Kernel 1: fused QKV projection (1x1 convs). One thread per (b, n) pixel.
// ---------------------------------------------------------------------------
__global__ __launch_bounds__(256) void qkv_kernel(
    const float* __restrict__ x,
    const float* __restrict__ wq, const float* __restrict__ bq,
    const float* __restrict__ wk, const float* __restrict__ bk,
    const float* __restrict__ wv, const float* __restrict__ bv)
{
    __shared__ float swq[DQ * CCH];
    __shared__ float swk[DQ * CCH];
    __shared__ float swv[CCH * CCH];
    __shared__ float sbq[DQ], sbk[DQ], sbv[CCH];

    const int tid = threadIdx.x;
    for (int i = tid; i < DQ * CCH; i += 256) { swq[i] = wq[i]; swk[i] = wk[i]; }
    for (int i = tid; i < CCH * CCH; i += 256) swv[i] = wv[i];
    if (tid < DQ) { sbq[tid] = bq[tid]; sbk[tid] = bk[tid]; }
    if (tid < CCH) sbv[tid] = bv[tid];
    __syncthreads();

    const int b = blockIdx.y;
    const int n = blockIdx.x * 256 + tid;

    // Load x column: x[b][c][n], coalesced across threads (n contiguous)
    float xv[CCH];
    const float* xb = x + ((size_t)b * CCH) * NPIX + n;
    #pragma unroll
    for (int c = 0; c < CCH; c++) xv[c] = xb[(size_t)c * NPIX];

    // q, k
    float qv[DQ], kv[DQ];
    #pragma unroll
    for (int d = 0; d < DQ; d++) {
        float aq = sbq[d], ak = sbk[d];
        #pragma unroll
        for (int c = 0; c < CCH; c++) {
            aq = fmaf(swq[d * CCH + c], xv[c], aq);
            ak = fmaf(swk[d * CCH + c], xv[c], ak);
        }
        qv[d] = aq; kv[d] = ak;
    }
    {
        float* qo = g_q + ((size_t)b * NPIX + n) * DQ;
        float* ko = g_k + ((size_t)b * NPIX + n) * DQ;
        ((float4*)qo)[0] = make_float4(qv[0], qv[1], qv[2], qv[3]);
        ((float4*)qo)[1] = make_float4(qv[4], qv[5], qv[6], qv[7]);
        ((float4*)ko)[0] = make_float4(kv[0], kv[1], kv[2], kv[3]);
        ((float4*)ko)[1] = make_float4(kv[4], kv[5], kv[6], kv[7]);
    }

    // v: 64 outputs
    float* vo = g_v + ((size_t)b * NPIX + n) * CCH;
    #pragma unroll 4
    for (int o = 0; o < CCH; o += 4) {
        float a0 = sbv[o + 0], a1 = sbv[o + 1], a2 = sbv[o + 2], a3 = sbv[o + 3];
        #pragma unroll
        for (int c = 0; c < CCH; c++) {
            float xc = xv[c];
            a0 = fmaf(swv[(o + 0) * CCH + c], xc, a0);
            a1 = fmaf(swv[(o + 1) * CCH + c], xc, a1);
            a2 = fmaf(swv[(o + 2) * CCH + c], xc, a2);
            a3 = fmaf(swv[(o + 3) * CCH + c], xc, a3);
        }
        ((float4*)(vo + o))[0] = make_float4(a0, a1, a2, a3);
    }
}

// ---------------------------------------------------------------------------
// Kernel 2: fused flash attention + gamma*out + x residual.
// Grid: (NPIX/TM, BATCH). 128 threads; thread t owns row m = blk*TM + t.
// ---------------------------------------------------------------------------
__global__ __launch_bounds__(TM) void attn_kernel(
    const float* __restrict__ x,
    const float* __restrict__ gamma,
    float* __restrict__ out)
{
    __shared__ float4 Ks[TN * 2];   // [n][8] -> 2 float4 per n
    __shared__ float4 Vs[TN * 16];  // [n][64] -> 16 float4 per n

    const int b = blockIdx.y;
    const int m = blockIdx.x * TM + threadIdx.x;

    // Per-row query (8 floats)
    const float4* qp = (const float4*)(g_q + ((size_t)b * NPIX + m) * DQ);
    const float4 q0 = qp[0];
    const float4 q1 = qp[1];

    float acc[CCH];
    #pragma unroll
    for (int c = 0; c < CCH; c++) acc[c] = 0.f;
    float mrun = -1e30f;
    float lsum = 0.f;

    for (int t = 0; t < NPIX; t += TN) {
        __syncthreads();  // protect prior tile consumption
        // Stage K tile: 256 float4, 2 per thread
        const float4* kt = (const float4*)(g_k + ((size_t)b * NPIX + t) * DQ);
        Ks[threadIdx.x]       = kt[threadIdx.x];
        Ks[threadIdx.x + 128] = kt[threadIdx.x + 128];
        // Stage V tile: 2048 float4, 16 per thread
        const float4* vt = (const float4*)(g_v + ((size_t)b * NPIX + t) * CCH);
        #pragma unroll
        for (int i = 0; i < 16; i++)
            Vs[threadIdx.x + i * 128] = vt[threadIdx.x + i * 128];
        __syncthreads();

        // Pass 1: tile max (dot recompute is only 8 FMA/n)
        float tmax = -1e30f;
        #pragma unroll 4
        for (int n = 0; n < TN; n++) {
            float4 k0 = Ks[n * 2], k1 = Ks[n * 2 + 1];
            float sA = q0.x * k0.x + q0.y * k0.y + q0.z * k0.z + q0.w * k0.w;
            float sB = q1.x * k1.x + q1.y * k1.y + q1.z * k1.z + q1.w * k1.w;
            tmax = fmaxf(tmax, sA + sB);
        }
        float mnew = fmaxf(mrun, tmax);
        float corr = __expf(mrun - mnew);   // 0 on first tile (mrun=-1e30)
        lsum *= corr;
        #pragma unroll
        for (int c = 0; c < CCH; c++) acc[c] *= corr;
        mrun = mnew;

        // Pass 2: exp + PV accumulate
        #pragma unroll 2
        for (int n = 0; n < TN; n++) {
            float4 k0 = Ks[n * 2], k1 = Ks[n * 2 + 1];
            float sA = q0.x * k0.x + q0.y * k0.y + q0.z * k0.z + q0.w * k0.w;
            float sB = q1.x * k1.x + q1.y * k1.y + q1.z * k1.z + q1.w * k1.w;
            float p = __expf((sA + sB) - mnew);
            lsum += p;
            const float4* vrow = &Vs[n * 16];
            #pragma unroll
            for (int i = 0; i < 16; i++) {
                float4 v4 = vrow[i];
                acc[i * 4 + 0] = fmaf(p, v4.x, acc[i * 4 + 0]);
                acc[i * 4 + 1] = fmaf(p, v4.y, acc[i * 4 + 1]);
                acc[i * 4 + 2] = fmaf(p, v4.z, acc[i * 4 + 2]);
                acc[i * 4 + 3] = fmaf(p, v4.w, acc[i * 4 + 3]);
            }
        }
    }

    // Epilogue: out[b][c][m] = gamma * acc[c]/lsum + x[b][c][m]
    const float g = gamma[0];
    const float inv = 1.f / lsum;
    const float* xb = x + ((size_t)b * CCH) * NPIX + m;
    float* ob = out + ((size_t)b * CCH) * NPIX + m;
    #pragma unroll
    for (int c = 0; c < CCH; c++) {
        ob[(size_t)c * NPIX] = fmaf(g, acc[c] * inv, xb[(size_t)c * NPIX]);
    }
}

// ---------------------------------------------------------------------------
extern "C" void kernel_launch(void* const* d_in, const int* in_sizes, int n_in,
                              void* d_out, int out_size)
{
    const float* x     = (const float*)d_in[0];
    const float* wq    = (const float*)d_in[1];
    const float* bq    = (const float*)d_in[2];
    const float* wk    = (const float*)d_in[3];
    const float* bk    = (const float*)d_in[4];
    const float* wv    = (const float*)d_in[5];
    const float* bv    = (const float*)d_in[6];
    const float* gamma = (const float*)d_in[7];
    float* out = (float*)d_out;

    dim3 g1(NPIX / 256, BATCH);
    qkv_kernel<<<g1, 256>>>(x, wq, bq, wk, bk, wv, bv);

    dim3 g2(NPIX / TM, BATCH);
    attn_kernel<<<g2, TM>>>(x, gamma, out);
}

// round 3
// speedup vs baseline: 6.1556x; 6.1556x over previous
#include <cuda_runtime.h>
#include <cuda_fp16.h>
#include <cstdint>

#define BATCH 8
#define CCH   64
#define DQ    8
#define NPIX  4096
#define TM    128
#define TN    128
#define NT    (NPIX / TN)
#define L2E   1.4426950408889634f

__device__ float g_q[BATCH * NPIX * DQ];
__device__ float g_k[BATCH * NPIX * DQ];
__device__ float g_qn[BATCH * NPIX];
__device__ float g_v[(size_t)BATCH * CCH * NPIX];   // [b][c][n]
__device__ int   g_kmax_i[BATCH];

// ---------------------------------------------------------------------------
__global__ void init_kmax_kernel() {
    if (threadIdx.x < BATCH) g_kmax_i[threadIdx.x] = 0;
}

// ---------------------------------------------------------------------------
// QKV projection: q,k -> [b][n][8] (+ row norms), v -> [b][c][n], k-norm max.
// ---------------------------------------------------------------------------
__global__ __launch_bounds__(256) void qkv_kernel(
    const float* __restrict__ x,
    const float* __restrict__ wq, const float* __restrict__ bq,
    const float* __restrict__ wk, const float* __restrict__ bk,
    const float* __restrict__ wv, const float* __restrict__ bv)
{
    __shared__ float swq[DQ * CCH], swk[DQ * CCH], swv[CCH * CCH];
    __shared__ float sbq[DQ], sbk[DQ], sbv[CCH];

    const int tid = threadIdx.x;
    for (int i = tid; i < DQ * CCH; i += 256) { swq[i] = wq[i]; swk[i] = wk[i]; }
    for (int i = tid; i < CCH * CCH; i += 256) swv[i] = wv[i];
    if (tid < DQ) { sbq[tid] = bq[tid]; sbk[tid] = bk[tid]; }
    if (tid < CCH) sbv[tid] = bv[tid];
    __syncthreads();

    const int b = blockIdx.y;
    const int n = blockIdx.x * 256 + tid;

    float xv[CCH];
    const float* xb = x + ((size_t)b * CCH) * NPIX + n;
    #pragma unroll
    for (int c = 0; c < CCH; c++) xv[c] = xb[(size_t)c * NPIX];

    float qv[DQ], kv[DQ];
    #pragma unroll
    for (int d = 0; d < DQ; d++) {
        float aq = sbq[d], ak = sbk[d];
        #pragma unroll
        for (int c = 0; c < CCH; c++) {
            aq = fmaf(swq[d * CCH + c], xv[c], aq);
            ak = fmaf(swk[d * CCH + c], xv[c], ak);
        }
        qv[d] = aq; kv[d] = ak;
    }
    {
        float* qo = g_q + ((size_t)b * NPIX + n) * DQ;
        float* ko = g_k + ((size_t)b * NPIX + n) * DQ;
        ((float4*)qo)[0] = make_float4(qv[0], qv[1], qv[2], qv[3]);
        ((float4*)qo)[1] = make_float4(qv[4], qv[5], qv[6], qv[7]);
        ((float4*)ko)[0] = make_float4(kv[0], kv[1], kv[2], kv[3]);
        ((float4*)ko)[1] = make_float4(kv[4], kv[5], kv[6], kv[7]);
    }
    {
        float nq2 = 0.f, nk2 = 0.f;
        #pragma unroll
        for (int d = 0; d < DQ; d++) {
            nq2 = fmaf(qv[d], qv[d], nq2);
            nk2 = fmaf(kv[d], kv[d], nk2);
        }
        g_qn[b * NPIX + n] = sqrtf(nq2);
        float nk = sqrtf(nk2);
        #pragma unroll
        for (int off = 16; off > 0; off >>= 1)
            nk = fmaxf(nk, __shfl_xor_sync(0xFFFFFFFFu, nk, off));
        if ((tid & 31) == 0) atomicMax(&g_kmax_i[b], __float_as_int(nk));
    }
    #pragma unroll 4
    for (int o = 0; o < CCH; o += 4) {
        float a0 = sbv[o+0], a1 = sbv[o+1], a2 = sbv[o+2], a3 = sbv[o+3];
        #pragma unroll
        for (int c = 0; c < CCH; c++) {
            float xc = xv[c];
            a0 = fmaf(swv[(o+0)*CCH + c], xc, a0);
            a1 = fmaf(swv[(o+1)*CCH + c], xc, a1);
            a2 = fmaf(swv[(o+2)*CCH + c], xc, a2);
            a3 = fmaf(swv[(o+3)*CCH + c], xc, a3);
        }
        g_v[((size_t)(b*CCH + o+0))*NPIX + n] = a0;
        g_v[((size_t)(b*CCH + o+1))*NPIX + n] = a1;
        g_v[((size_t)(b*CCH + o+2))*NPIX + n] = a2;
        g_v[((size_t)(b*CCH + o+3))*NPIX + n] = a3;
    }
}

// ---------------------------------------------------------------------------
// Fused flash attention with warp-level mma.sync (HMMA).
// Grid (32, 8), 128 threads (4 warps). Warp w owns 32 m-rows (2 m16 tiles).
// S = QK^T * log2e - shift via tf32 m16n8k8 (shift in C-init).
// P = ex2(S) in f16x2 via MUFU. PV via f16 m16n8k16.
// ---------------------------------------------------------------------------
__global__ __launch_bounds__(128) void attn_kernel(
    const float* __restrict__ x,
    const float* __restrict__ gamma,
    float* __restrict__ out)
{
    __shared__ __align__(16) uint32_t sK[TN][12];      // tf32 bits, padded (conflict-free B-frag loads)
    __shared__ __align__(16) uint16_t sVT[CCH][136];   // f16 V^T [ch][pix], padded
    __shared__ __align__(16) uint16_t sP[4][32][40];   // per-warp P chunk f16, padded

    const int tid  = threadIdx.x;
    const int w    = tid >> 5;
    const int lane = tid & 31;
    const int g    = lane >> 2;     // group id (0..7)
    const int c    = lane & 3;      // thread in group (0..3)
    const int b    = blockIdx.y;
    const int m0   = blockIdx.x * TM + w * 32;

    // Q fragments (tf32, *log2e) and -shift per owned row
    uint32_t qa[2][4];
    float nsh[4];
    {
        const float kmax = __int_as_float(g_kmax_i[b]);
        #pragma unroll
        for (int mt = 0; mt < 2; mt++) {
            const int rA = m0 + mt * 16 + g;
            const int rB = rA + 8;
            const float* qA = g_q + ((size_t)b * NPIX + rA) * DQ;
            const float* qB = g_q + ((size_t)b * NPIX + rB) * DQ;
            float f0 = qA[c] * L2E, f1 = qB[c] * L2E, f2 = qA[c + 4] * L2E, f3 = qB[c + 4] * L2E;
            asm("cvt.rna.tf32.f32 %0, %1;" : "=r"(qa[mt][0]) : "f"(f0));
            asm("cvt.rna.tf32.f32 %0, %1;" : "=r"(qa[mt][1]) : "f"(f1));
            asm("cvt.rna.tf32.f32 %0, %1;" : "=r"(qa[mt][2]) : "f"(f2));
            asm("cvt.rna.tf32.f32 %0, %1;" : "=r"(qa[mt][3]) : "f"(f3));
            nsh[mt * 2 + 0] = -g_qn[b * NPIX + rA] * kmax * L2E;
            nsh[mt * 2 + 1] = -g_qn[b * NPIX + rB] * kmax * L2E;
        }
    }

    float acc[2][8][4];
    #pragma unroll
    for (int mt = 0; mt < 2; mt++)
        #pragma unroll
        for (int jc = 0; jc < 8; jc++)
            #pragma unroll
            for (int r = 0; r < 4; r++) acc[mt][jc][r] = 0.f;
    float ls[4] = {0.f, 0.f, 0.f, 0.f};

    for (int t = 0; t < NT; t++) {
        const int t0 = t * TN;
        if (t) __syncthreads();

        // Stage K tile (tf32 bits), one row per thread
        {
            const float4* kr = (const float4*)(g_k + ((size_t)b * NPIX + t0 + tid) * DQ);
            float4 k0 = kr[0], k1 = kr[1];
            uint32_t kk[8];
            asm("cvt.rna.tf32.f32 %0, %1;" : "=r"(kk[0]) : "f"(k0.x));
            asm("cvt.rna.tf32.f32 %0, %1;" : "=r"(kk[1]) : "f"(k0.y));
            asm("cvt.rna.tf32.f32 %0, %1;" : "=r"(kk[2]) : "f"(k0.z));
            asm("cvt.rna.tf32.f32 %0, %1;" : "=r"(kk[3]) : "f"(k0.w));
            asm("cvt.rna.tf32.f32 %0, %1;" : "=r"(kk[4]) : "f"(k1.x));
            asm("cvt.rna.tf32.f32 %0, %1;" : "=r"(kk[5]) : "f"(k1.y));
            asm("cvt.rna.tf32.f32 %0, %1;" : "=r"(kk[6]) : "f"(k1.z));
            asm("cvt.rna.tf32.f32 %0, %1;" : "=r"(kk[7]) : "f"(k1.w));
            *(uint4*)&sK[tid][0] = make_uint4(kk[0], kk[1], kk[2], kk[3]);
            *(uint4*)&sK[tid][4] = make_uint4(kk[4], kk[5], kk[6], kk[7]);
        }
        // Stage V^T tile as f16
        #pragma unroll
        for (int i = 0; i < 16; i++) {
            int idx = tid + i * 128;
            int ch = idx >> 5, pg = idx & 31;
            float4 v = *(const float4*)(g_v + ((size_t)(b * CCH + ch)) * NPIX + t0 + pg * 4);
            uint32_t p0, p1;
            asm("cvt.rn.f16x2.f32 %0, %1, %2;" : "=r"(p0) : "f"(v.y), "f"(v.x));
            asm("cvt.rn.f16x2.f32 %0, %1, %2;" : "=r"(p1) : "f"(v.w), "f"(v.z));
            *(uint2*)&sVT[ch][pg * 4] = make_uint2(p0, p1);
        }
        __syncthreads();

        #pragma unroll
        for (int ch4 = 0; ch4 < 4; ch4++) {
            // --- S mma + exp ---
            uint32_t pp[2][4][2];
            #pragma unroll
            for (int j = 0; j < 4; j++) {
                const int n8 = ch4 * 4 + j;
                const uint32_t kb0 = sK[n8 * 8 + g][c];
                const uint32_t kb1 = sK[n8 * 8 + g][c + 4];
                #pragma unroll
                for (int mt = 0; mt < 2; mt++) {
                    float s0, s1, s2, s3;
                    asm volatile(
                        "mma.sync.aligned.m16n8k8.row.col.f32.tf32.tf32.f32 "
                        "{%0,%1,%2,%3}, {%4,%5,%6,%7}, {%8,%9}, {%10,%11,%12,%13};"
                        : "=f"(s0), "=f"(s1), "=f"(s2), "=f"(s3)
                        : "r"(qa[mt][0]), "r"(qa[mt][1]), "r"(qa[mt][2]), "r"(qa[mt][3]),
                          "r"(kb0), "r"(kb1),
                          "f"(nsh[mt*2]), "f"(nsh[mt*2]), "f"(nsh[mt*2+1]), "f"(nsh[mt*2+1]));
                    uint32_t u0, u1, pA, pB;
                    asm("cvt.rn.f16x2.f32 %0, %1, %2;" : "=r"(u0) : "f"(s1), "f"(s0));
                    asm("cvt.rn.f16x2.f32 %0, %1, %2;" : "=r"(u1) : "f"(s3), "f"(s2));
                    asm("ex2.approx.f16x2 %0, %1;" : "=r"(pA) : "r"(u0));
                    asm("ex2.approx.f16x2 %0, %1;" : "=r"(pB) : "r"(u1));
                    pp[mt][j][0] = pA;
                    pp[mt][j][1] = pB;
                    float2 fA = __half22float2(*(__half2*)&pA);
                    float2 fB = __half22float2(*(__half2*)&pB);
                    ls[mt * 2 + 0] += fA.x + fA.y;
                    ls[mt * 2 + 1] += fB.x + fB.y;
                }
            }
            // --- store P chunk ---
            #pragma unroll
            for (int j = 0; j < 4; j++) {
                #pragma unroll
                for (int mt = 0; mt < 2; mt++) {
                    *(uint32_t*)&sP[w][mt * 16 + g][j * 8 + 2 * c]     = pp[mt][j][0];
                    *(uint32_t*)&sP[w][mt * 16 + g + 8][j * 8 + 2 * c] = pp[mt][j][1];
                }
            }
            __syncwarp();
            // --- PV mma ---
            #pragma unroll
            for (int ks = 0; ks < 2; ks++) {
                uint32_t a[2][4];
                #pragma unroll
                for (int mt = 0; mt < 2; mt++) {
                    a[mt][0] = *(uint32_t*)&sP[w][mt * 16 + g][ks * 16 + 2 * c];
                    a[mt][1] = *(uint32_t*)&sP[w][mt * 16 + g + 8][ks * 16 + 2 * c];
                    a[mt][2] = *(uint32_t*)&sP[w][mt * 16 + g][ks * 16 + 2 * c + 8];
                    a[mt][3] = *(uint32_t*)&sP[w][mt * 16 + g + 8][ks * 16 + 2 * c + 8];
                }
                const int kp = ch4 * 32 + ks * 16;
                #pragma unroll
                for (int jc = 0; jc < 8; jc++) {
                    const uint32_t b0 = *(uint32_t*)&sVT[jc * 8 + g][kp + 2 * c];
                    const uint32_t b1 = *(uint32_t*)&sVT[jc * 8 + g][kp + 2 * c + 8];
                    #pragma unroll
                    for (int mt = 0; mt < 2; mt++) {
                        asm volatile(
                            "mma.sync.aligned.m16n8k16.row.col.f32.f16.f16.f32 "
                            "{%0,%1,%2,%3}, {%4,%5,%6,%7}, {%8,%9}, {%0,%1,%2,%3};"
                            : "+f"(acc[mt][jc][0]), "+f"(acc[mt][jc][1]),
                              "+f"(acc[mt][jc][2]), "+f"(acc[mt][jc][3])
                            : "r"(a[mt][0]), "r"(a[mt][1]), "r"(a[mt][2]), "r"(a[mt][3]),
                              "r"(b0), "r"(b1));
                    }
                }
            }
            __syncwarp();
        }
    }

    // lsum reduce across the 4 lanes sharing each row
    #pragma unroll
    for (int i = 0; i < 4; i++) {
        ls[i] += __shfl_xor_sync(0xFFFFFFFFu, ls[i], 1);
        ls[i] += __shfl_xor_sync(0xFFFFFFFFu, ls[i], 2);
    }
    float inv[4];
    #pragma unroll
    for (int i = 0; i < 4; i++) inv[i] = 1.f / ls[i];

    const float gm = gamma[0];
    const float* xb = x   + (size_t)b * CCH * NPIX;
    float*       ob = out + (size_t)b * CCH * NPIX;
    #pragma unroll
    for (int mt = 0; mt < 2; mt++) {
        const int rA = m0 + mt * 16 + g;
        const int rB = rA + 8;
        const float iA = inv[mt * 2 + 0];
        const float iB = inv[mt * 2 + 1];
        #pragma unroll
        for (int jc = 0; jc < 8; jc++) {
            const int ch0 = jc * 8 + 2 * c;
            const int ch1 = ch0 + 1;
            ob[(size_t)ch0 * NPIX + rA] = fmaf(gm, acc[mt][jc][0] * iA, xb[(size_t)ch0 * NPIX + rA]);
            ob[(size_t)ch1 * NPIX + rA] = fmaf(gm, acc[mt][jc][1] * iA, xb[(size_t)ch1 * NPIX + rA]);
            ob[(size_t)ch0 * NPIX + rB] = fmaf(gm, acc[mt][jc][2] * iB, xb[(size_t)ch0 * NPIX + rB]);
            ob[(size_t)ch1 * NPIX + rB] = fmaf(gm, acc[mt][jc][3] * iB, xb[(size_t)ch1 * NPIX + rB]);
        }
    }
}

// ---------------------------------------------------------------------------
extern "C" void kernel_launch(void* const* d_in, const int* in_sizes, int n_in,
                              void* d_out, int out_size)
{
    const float* x     = (const float*)d_in[0];
    const float* wq    = (const float*)d_in[1];
    const float* bq    = (const float*)d_in[2];
    const float* wk    = (const float*)d_in[3];
    const float* bk    = (const float*)d_in[4];
    const float* wv    = (const float*)d_in[5];
    const float* bv    = (const float*)d_in[6];
    const float* gamma = (const float*)d_in[7];
    float* out = (float*)d_out;

    init_kmax_kernel<<<1, 32>>>();
    dim3 g1(NPIX / 256, BATCH);
    qkv_kernel<<<g1, 256>>>(x, wq, bq, wk, bk, wv, bv);
    dim3 g2(NPIX / TM, BATCH);
    attn_kernel<<<g2, TM>>>(x, gamma, out);
}

// round 4
// speedup vs baseline: 8.3239x; 1.3522x over previous
#include <cuda_runtime.h>
#include <cuda_fp16.h>
#include <cstdint>

#define BATCH 8
#define CCH   64
#define DQ    8
#define NPIX  4096
#define TM    128
#define TN    128
#define NT    (NPIX / TN)
#define L2E   1.4426950408889634f

__device__ __half g_q16[BATCH * NPIX * DQ];                 // pre-scaled by log2(e)
__device__ __half g_k16[BATCH * NPIX * DQ];
__device__ float  g_qn[BATCH * NPIX];
__device__ __half g_v16[(size_t)BATCH * CCH * NPIX];        // [b][c][n]
__device__ float  g_kmax_part[BATCH * 16];

__device__ __forceinline__ uint32_t s2u(const void* p) {
    uint32_t a;
    asm("{ .reg .u64 t; cvta.to.shared.u64 t, %1; cvt.u32.u64 %0, t; }" : "=r"(a) : "l"(p));
    return a;
}
#define CP16(dst, src) asm volatile("cp.async.cg.shared.global [%0], [%1], 16;" :: "r"(dst), "l"(src) : "memory")
#define CPCOMMIT()     asm volatile("cp.async.commit_group;" ::: "memory")
#define CPWAIT1()      asm volatile("cp.async.wait_group 1;" ::: "memory")
#define CPWAIT0()      asm volatile("cp.async.wait_group 0;" ::: "memory")

// ---------------------------------------------------------------------------
// QKV projection: q,k -> f16 [b][n][8] (q pre-scaled by log2e), v -> f16 [b][c][n],
// |q| row norms, per-block |k| max partials.
// ---------------------------------------------------------------------------
__global__ __launch_bounds__(256) void qkv_kernel(
    const float* __restrict__ x,
    const float* __restrict__ wq, const float* __restrict__ bq,
    const float* __restrict__ wk, const float* __restrict__ bk,
    const float* __restrict__ wv, const float* __restrict__ bv)
{
    __shared__ float swq[DQ * CCH], swk[DQ * CCH], swv[CCH * CCH];
    __shared__ float sbq[DQ], sbk[DQ], sbv[CCH];
    __shared__ float swmax[8];

    const int tid = threadIdx.x;
    for (int i = tid; i < DQ * CCH; i += 256) { swq[i] = wq[i]; swk[i] = wk[i]; }
    for (int i = tid; i < CCH * CCH; i += 256) swv[i] = wv[i];
    if (tid < DQ) { sbq[tid] = bq[tid]; sbk[tid] = bk[tid]; }
    if (tid < CCH) sbv[tid] = bv[tid];
    __syncthreads();

    const int b = blockIdx.y;
    const int n = blockIdx.x * 256 + tid;

    float xv[CCH];
    const float* xb = x + ((size_t)b * CCH) * NPIX + n;
    #pragma unroll
    for (int c = 0; c < CCH; c++) xv[c] = xb[(size_t)c * NPIX];

    float qv[DQ], kv[DQ];
    #pragma unroll
    for (int d = 0; d < DQ; d++) {
        float aq = sbq[d], ak = sbk[d];
        #pragma unroll
        for (int c = 0; c < CCH; c++) {
            aq = fmaf(swq[d * CCH + c], xv[c], aq);
            ak = fmaf(swk[d * CCH + c], xv[c], ak);
        }
        qv[d] = aq; kv[d] = ak;
    }
    {
        __half2* qo = (__half2*)&g_q16[((size_t)b * NPIX + n) * DQ];
        __half2* ko = (__half2*)&g_k16[((size_t)b * NPIX + n) * DQ];
        #pragma unroll
        for (int d = 0; d < 4; d++) {
            qo[d] = __floats2half2_rn(qv[2*d] * L2E, qv[2*d+1] * L2E);
            ko[d] = __floats2half2_rn(kv[2*d], kv[2*d+1]);
        }
    }
    {
        float nq2 = 0.f, nk2 = 0.f;
        #pragma unroll
        for (int d = 0; d < DQ; d++) {
            nq2 = fmaf(qv[d], qv[d], nq2);
            nk2 = fmaf(kv[d], kv[d], nk2);
        }
        g_qn[b * NPIX + n] = sqrtf(nq2);
        float nk = sqrtf(nk2);
        #pragma unroll
        for (int off = 16; off > 0; off >>= 1)
            nk = fmaxf(nk, __shfl_xor_sync(0xFFFFFFFFu, nk, off));
        if ((tid & 31) == 0) swmax[tid >> 5] = nk;
        __syncthreads();
        if (tid == 0) {
            float m = swmax[0];
            #pragma unroll
            for (int i = 1; i < 8; i++) m = fmaxf(m, swmax[i]);
            g_kmax_part[b * 16 + blockIdx.x] = m;
        }
    }
    #pragma unroll 4
    for (int o = 0; o < CCH; o += 4) {
        float a0 = sbv[o+0], a1 = sbv[o+1], a2 = sbv[o+2], a3 = sbv[o+3];
        #pragma unroll
        for (int c = 0; c < CCH; c++) {
            float xc = xv[c];
            a0 = fmaf(swv[(o+0)*CCH + c], xc, a0);
            a1 = fmaf(swv[(o+1)*CCH + c], xc, a1);
            a2 = fmaf(swv[(o+2)*CCH + c], xc, a2);
            a3 = fmaf(swv[(o+3)*CCH + c], xc, a3);
        }
        g_v16[((size_t)(b*CCH + o+0))*NPIX + n] = __float2half_rn(a0);
        g_v16[((size_t)(b*CCH + o+1))*NPIX + n] = __float2half_rn(a1);
        g_v16[((size_t)(b*CCH + o+2))*NPIX + n] = __float2half_rn(a2);
        g_v16[((size_t)(b*CCH + o+3))*NPIX + n] = __float2half_rn(a3);
    }
}

// ---------------------------------------------------------------------------
// Fused flash attention, all-HMMA, register-direct P, cp.async double buffer.
// Grid (32, 8), 128 threads (4 warps); warp owns 32 m-rows.
// ---------------------------------------------------------------------------
#define STAGE(t, buf) do { \
    const __half* _ks = g_k16 + ((size_t)b * NPIX + (t) * TN + tid) * DQ; \
    CP16(s2u(&sK[buf][tid][0]), _ks); \
    _Pragma("unroll") \
    for (int _i = 0; _i < 8; _i++) { \
        int _l = _i * 128 + tid, _row = _l >> 4, _seg = _l & 15; \
        const __half* _vs = g_v16 + ((size_t)(b * CCH + _row)) * NPIX + (t) * TN + _seg * 8; \
        CP16(s2u(&sV[buf][_row][_seg * 8]), _vs); \
    } \
} while (0)

__global__ __launch_bounds__(128) void attn_kernel(
    const float* __restrict__ x,
    const float* __restrict__ gamma,
    float* __restrict__ out)
{
    __shared__ __align__(16) __half sK[2][TN][24];    // 48B row stride: conflict-free frags
    __shared__ __align__(16) __half sV[2][CCH][136];  // 272B row stride

    const int tid  = threadIdx.x;
    const int w    = tid >> 5;
    const int lane = tid & 31;
    const int g    = lane >> 2;
    const int c    = lane & 3;
    const int b    = blockIdx.y;
    const int m0   = blockIdx.x * TM + w * 32;

    float kmax = g_kmax_part[b * 16];
    #pragma unroll
    for (int i = 1; i < 16; i++) kmax = fmaxf(kmax, g_kmax_part[b * 16 + i]);

    uint32_t qa0[2], qa1[2];
    float nsh[4];
    #pragma unroll
    for (int mt = 0; mt < 2; mt++) {
        const int rA = m0 + mt * 16 + g, rB = rA + 8;
        qa0[mt] = *(const uint32_t*)&g_q16[((size_t)b * NPIX + rA) * DQ + 2 * c];
        qa1[mt] = *(const uint32_t*)&g_q16[((size_t)b * NPIX + rB) * DQ + 2 * c];
        nsh[2*mt]   = -g_qn[b * NPIX + rA] * kmax * L2E;
        nsh[2*mt+1] = -g_qn[b * NPIX + rB] * kmax * L2E;
    }

    float acc[2][9][4];
    #pragma unroll
    for (int mt = 0; mt < 2; mt++)
        #pragma unroll
        for (int jc = 0; jc < 9; jc++)
            #pragma unroll
            for (int r = 0; r < 4; r++) acc[mt][jc][r] = 0.f;

    STAGE(0, 0); CPCOMMIT();

    #pragma unroll 1
    for (int t = 0; t < NT; t++) {
        if (t + 1 < NT) { STAGE(t + 1, (t + 1) & 1); CPCOMMIT(); CPWAIT1(); }
        else            { CPWAIT0(); }
        __syncthreads();
        const __half (*K)[24]  = sK[t & 1];
        const __half (*V)[136] = sV[t & 1];

        #pragma unroll
        for (int kc = 0; kc < 8; kc++) {
            const uint32_t kb0 = *(const uint32_t*)&K[kc * 16 + g][2 * c];
            const uint32_t kb1 = *(const uint32_t*)&K[kc * 16 + 8 + g][2 * c];
            uint32_t pf[2][4];
            #pragma unroll
            for (int mt = 0; mt < 2; mt++) {
                float s0, s1, s2, s3;
                asm volatile(
                    "mma.sync.aligned.m16n8k8.row.col.f32.f16.f16.f32 "
                    "{%0,%1,%2,%3},{%4,%5},{%6},{%7,%8,%9,%10};"
                    : "=f"(s0), "=f"(s1), "=f"(s2), "=f"(s3)
                    : "r"(qa0[mt]), "r"(qa1[mt]), "r"(kb0),
                      "f"(nsh[2*mt]), "f"(nsh[2*mt]), "f"(nsh[2*mt+1]), "f"(nsh[2*mt+1]));
                uint32_t u0, u1;
                asm("cvt.rn.f16x2.f32 %0, %1, %2;" : "=r"(u0) : "f"(s1), "f"(s0));
                asm("cvt.rn.f16x2.f32 %0, %1, %2;" : "=r"(u1) : "f"(s3), "f"(s2));
                asm("ex2.approx.f16x2 %0, %1;" : "=r"(pf[mt][0]) : "r"(u0));
                asm("ex2.approx.f16x2 %0, %1;" : "=r"(pf[mt][1]) : "r"(u1));
                asm volatile(
                    "mma.sync.aligned.m16n8k8.row.col.f32.f16.f16.f32 "
                    "{%0,%1,%2,%3},{%4,%5},{%6},{%7,%8,%9,%10};"
                    : "=f"(s0), "=f"(s1), "=f"(s2), "=f"(s3)
                    : "r"(qa0[mt]), "r"(qa1[mt]), "r"(kb1),
                      "f"(nsh[2*mt]), "f"(nsh[2*mt]), "f"(nsh[2*mt+1]), "f"(nsh[2*mt+1]));
                asm("cvt.rn.f16x2.f32 %0, %1, %2;" : "=r"(u0) : "f"(s1), "f"(s0));
                asm("cvt.rn.f16x2.f32 %0, %1, %2;" : "=r"(u1) : "f"(s3), "f"(s2));
                asm("ex2.approx.f16x2 %0, %1;" : "=r"(pf[mt][2]) : "r"(u0));
                asm("ex2.approx.f16x2 %0, %1;" : "=r"(pf[mt][3]) : "r"(u1));
            }
            // PV: 8 V-channel tiles + 1 ones tile (lsum)
            #pragma unroll
            for (int jc = 0; jc < 8; jc++) {
                const uint32_t b0 = *(const uint32_t*)&V[jc * 8 + g][kc * 16 + 2 * c];
                const uint32_t b1 = *(const uint32_t*)&V[jc * 8 + g][kc * 16 + 2 * c + 8];
                #pragma unroll
                for (int mt = 0; mt < 2; mt++) {
                    asm volatile(
                        "mma.sync.aligned.m16n8k16.row.col.f32.f16.f16.f32 "
                        "{%0,%1,%2,%3},{%4,%5,%6,%7},{%8,%9},{%0,%1,%2,%3};"
                        : "+f"(acc[mt][jc][0]), "+f"(acc[mt][jc][1]),
                          "+f"(acc[mt][jc][2]), "+f"(acc[mt][jc][3])
                        : "r"(pf[mt][0]), "r"(pf[mt][1]), "r"(pf[mt][2]), "r"(pf[mt][3]),
                          "r"(b0), "r"(b1));
                }
            }
            {
                const uint32_t ones = (g == 0) ? 0x3C003C00u : 0u;
                #pragma unroll
                for (int mt = 0; mt < 2; mt++) {
                    asm volatile(
                        "mma.sync.aligned.m16n8k16.row.col.f32.f16.f16.f32 "
                        "{%0,%1,%2,%3},{%4,%5,%6,%7},{%8,%9},{%0,%1,%2,%3};"
                        : "+f"(acc[mt][8][0]), "+f"(acc[mt][8][1]),
                          "+f"(acc[mt][8][2]), "+f"(acc[mt][8][3])
                        : "r"(pf[mt][0]), "r"(pf[mt][1]), "r"(pf[mt][2]), "r"(pf[mt][3]),
                          "r"(ones), "r"(ones));
                }
            }
        }
        __syncthreads();
    }

    // Epilogue: lsum lives in acc[mt][8][0]/[2] on c==0 lanes; broadcast in quad.
    const float gm = gamma[0];
    const float* xb = x   + (size_t)b * CCH * NPIX;
    float*       ob = out + (size_t)b * CCH * NPIX;
    #pragma unroll
    for (int mt = 0; mt < 2; mt++) {
        const float lsA = __shfl_sync(0xFFFFFFFFu, acc[mt][8][0], lane & ~3);
        const float lsB = __shfl_sync(0xFFFFFFFFu, acc[mt][8][2], lane & ~3);
        const float iA = 1.f / lsA, iB = 1.f / lsB;
        const int rA = m0 + mt * 16 + g, rB = rA + 8;
        #pragma unroll
        for (int jc = 0; jc < 8; jc++) {
            const int ch0 = jc * 8 + 2 * c, ch1 = ch0 + 1;
            ob[(size_t)ch0 * NPIX + rA] = fmaf(gm, acc[mt][jc][0] * iA, xb[(size_t)ch0 * NPIX + rA]);
            ob[(size_t)ch1 * NPIX + rA] = fmaf(gm, acc[mt][jc][1] * iA, xb[(size_t)ch1 * NPIX + rA]);
            ob[(size_t)ch0 * NPIX + rB] = fmaf(gm, acc[mt][jc][2] * iB, xb[(size_t)ch0 * NPIX + rB]);
            ob[(size_t)ch1 * NPIX + rB] = fmaf(gm, acc[mt][jc][3] * iB, xb[(size_t)ch1 * NPIX + rB]);
        }
    }
}

// ---------------------------------------------------------------------------
extern "C" void kernel_launch(void* const* d_in, const int* in_sizes, int n_in,
                              void* d_out, int out_size)
{
    const float* x     = (const float*)d_in[0];
    const float* wq    = (const float*)d_in[1];
    const float* bq    = (const float*)d_in[2];
    const float* wk    = (const float*)d_in[3];
    const float* bk    = (const float*)d_in[4];
    const float* wv    = (const float*)d_in[5];
    const float* bv    = (const float*)d_in[6];
    const float* gamma = (const float*)d_in[7];
    float* out = (float*)d_out;

    dim3 g1(NPIX / 256, BATCH);
    qkv_kernel<<<g1, 256>>>(x, wq, bq, wk, bk, wv, bv);
    dim3 g2(NPIX / TM, BATCH);
    attn_kernel<<<g2, TM>>>(x, gamma, out);
}